// round 5
// baseline (speedup 1.0000x reference)
#include <cuda_runtime.h>
#include <math.h>

#define BB 16
#define PP 16384
#define MM 2048
#define D_Z 512
#define D_PHI 256
#define D_R 64
#define H1 96
#define H2 96

// scratch (no allocation allowed)
__device__ float g_A[BB * H1];
__device__ float g_Cp[PP * H1];

__device__ __forceinline__ float gelu_exact(float x) {
    return 0.5f * x * (1.0f + erff(x * 0.70710678118654752440f));
}

// ---------------------------------------------------------------------------
// Kernel A: A[b,j] = b1[j] + sum_k g_q[b,k] * W1[k,j]   (16 x 96, trivial)
// ---------------------------------------------------------------------------
__global__ void kA(const float* __restrict__ g_q,
                   const float* __restrict__ W1,
                   const float* __restrict__ b1) {
    int idx = blockIdx.x * blockDim.x + threadIdx.x;
    if (idx >= BB * H1) return;
    int b = idx / H1, j = idx % H1;
    float s = b1[j];
    const float* gq = g_q + b * D_Z;
    #pragma unroll 8
    for (int k = 0; k < D_Z; k++) s += gq[k] * W1[k * H1 + j];
    g_A[idx] = s;
}

// ---------------------------------------------------------------------------
// Kernel B: Cp[p,j] = sum_k' feat(p,k') * W1[512+k', j]
// feat(p, k'): k'<256 -> phi_i+phi_j ; <512 -> |phi_i-phi_j| ; <768 -> phi_i*phi_j
//              <832 -> relation[p, k'-768]
// pair_index dtype is detected on-device (int32 vs int64): for int64 data the
// odd 32-bit words (hi halves of values < 2^31) are all zero; for int32 data
// they are the j-indices and cannot all be zero over 64 random pairs.
// Tiling: 64 pairs/block, 256 threads, thread = (pg 0..31, jg 0..7),
// owns pairs {pg, pg+32} x 12 j outputs. K processed in 13 chunks of 64.
// ---------------------------------------------------------------------------
#define TPB 64
#define FS_STRIDE 68

__global__ void __launch_bounds__(256) kB(const float* __restrict__ Phi,
                                          const void* __restrict__ pair_index,
                                          const float* __restrict__ rel,
                                          const float* __restrict__ W1) {
    __shared__ float Fs[TPB * FS_STRIDE];   // feature chunk, padded
    __shared__ float Wc[64 * 96];           // weight chunk
    __shared__ int   pi_sh[TPB * 2];

    int tid = threadIdx.x;
    int p0 = blockIdx.x * TPB;

    // ---- dtype detection + index load (128 index values per block) ----
    {
        const int* p32 = (const int*)pair_index;
        int w = 0;
        if (tid < TPB * 2) w = p32[(size_t)p0 * 2 + tid];   // int32-layout read
        int any_odd = __syncthreads_or((tid & 1) ? w : 0);
        if (tid < TPB * 2) {
            int v;
            if (any_odd != 0) {
                v = w;                                       // int32 data
            } else {
                const long long* p64 = (const long long*)pair_index;
                v = (int)p64[(size_t)p0 * 2 + tid];          // int64 data
            }
            v = v < 0 ? 0 : (v >= MM ? MM - 1 : v);
            pi_sh[tid] = v;
        }
    }

    int jg = tid & 7;    // j group: columns jg*12 .. jg*12+11
    int pg = tid >> 3;   // 0..31

    float acc0[12], acc1[12];
    #pragma unroll
    for (int i = 0; i < 12; i++) { acc0[i] = 0.f; acc1[i] = 0.f; }

    for (int kc = 0; kc < 13; kc++) {
        int mode  = kc >> 2;          // 0:sum 1:absdiff 2:prod 3:relation
        int cbase = (kc & 3) * 64;
        __syncthreads();              // protect Fs/Wc from previous iter readers
        // build feature chunk
        for (int t = tid; t < TPB * 64; t += 256) {
            int pp = t >> 6, kk = t & 63;
            float f;
            if (mode == 3) {
                f = rel[(size_t)(p0 + pp) * D_R + kk];
            } else {
                int i0 = pi_sh[pp * 2];
                int j0 = pi_sh[pp * 2 + 1];
                float a = Phi[i0 * D_PHI + cbase + kk];
                float c = Phi[j0 * D_PHI + cbase + kk];
                f = (mode == 0) ? (a + c) : (mode == 1) ? fabsf(a - c) : (a * c);
            }
            Fs[pp * FS_STRIDE + kk] = f;
        }
        // load weight chunk rows 512 + kc*64 .. +63  (as float4)
        for (int t = tid; t < 64 * 24; t += 256) {
            int kk = t / 24, c4 = t % 24;
            ((float4*)Wc)[kk * 24 + c4] =
                ((const float4*)(W1 + (size_t)(D_Z + kc * 64 + kk) * H1))[c4];
        }
        __syncthreads();

        #pragma unroll 4
        for (int kk = 0; kk < 64; kk++) {
            float f0 = Fs[pg * FS_STRIDE + kk];
            float f1 = Fs[(pg + 32) * FS_STRIDE + kk];
            const float4* w = (const float4*)(Wc + kk * 96 + jg * 12);
            float4 a0 = w[0], a1 = w[1], a2 = w[2];
            acc0[0]  += f0 * a0.x; acc1[0]  += f1 * a0.x;
            acc0[1]  += f0 * a0.y; acc1[1]  += f1 * a0.y;
            acc0[2]  += f0 * a0.z; acc1[2]  += f1 * a0.z;
            acc0[3]  += f0 * a0.w; acc1[3]  += f1 * a0.w;
            acc0[4]  += f0 * a1.x; acc1[4]  += f1 * a1.x;
            acc0[5]  += f0 * a1.y; acc1[5]  += f1 * a1.y;
            acc0[6]  += f0 * a1.z; acc1[6]  += f1 * a1.z;
            acc0[7]  += f0 * a1.w; acc1[7]  += f1 * a1.w;
            acc0[8]  += f0 * a2.x; acc1[8]  += f1 * a2.x;
            acc0[9]  += f0 * a2.y; acc1[9]  += f1 * a2.y;
            acc0[10] += f0 * a2.z; acc1[10] += f1 * a2.z;
            acc0[11] += f0 * a2.w; acc1[11] += f1 * a2.w;
        }
    }

    float* o0 = g_Cp + (size_t)(p0 + pg) * H1 + jg * 12;
    float* o1 = g_Cp + (size_t)(p0 + pg + 32) * H1 + jg * 12;
    ((float4*)o0)[0] = make_float4(acc0[0], acc0[1], acc0[2], acc0[3]);
    ((float4*)o0)[1] = make_float4(acc0[4], acc0[5], acc0[6], acc0[7]);
    ((float4*)o0)[2] = make_float4(acc0[8], acc0[9], acc0[10], acc0[11]);
    ((float4*)o1)[0] = make_float4(acc1[0], acc1[1], acc1[2], acc1[3]);
    ((float4*)o1)[1] = make_float4(acc1[4], acc1[5], acc1[6], acc1[7]);
    ((float4*)o1)[2] = make_float4(acc1[8], acc1[9], acc1[10], acc1[11]);
}

// ---------------------------------------------------------------------------
// Kernel C: out[b,p] = gelu(gelu(A[b]+Cp[p]) @ W2 + b2) @ W3 + b3
// Block: 8 pairs x 16 b = 128 rows, one thread per row.
// 96 accumulators (h2 pre-activation) in REGISTERS; stream k over h1:
//   v = gelu(A[b,k] + Cp[p,k]);  s[j] += v * W2[k,j]  (W2 row broadcast from smem)
// Static smem: 36864 (W2) + 6208 (A pad97) + 3104 (Cp pad97) + 768 = 46.9 KB
// ---------------------------------------------------------------------------
#define CPAIRS 8

__global__ void __launch_bounds__(128) kC(const float* __restrict__ W2,
                                          const float* __restrict__ b2,
                                          const float* __restrict__ W3,
                                          const float* __restrict__ b3,
                                          float* __restrict__ out) {
    __shared__ float W2sh[96 * 96];
    __shared__ float Ash[16 * 97];
    __shared__ float Cpsh[CPAIRS * 97];
    __shared__ float W3sh[96];
    __shared__ float b2sh[96];

    int tid = threadIdx.x;
    int p0 = blockIdx.x * CPAIRS;

    for (int t = tid; t < 2304; t += 128)
        ((float4*)W2sh)[t] = ((const float4*)W2)[t];
    for (int t = tid; t < BB * H1; t += 128) {
        int b = t / 96, k = t - b * 96;
        Ash[b * 97 + k] = g_A[t];
    }
    for (int t = tid; t < CPAIRS * H1; t += 128) {
        int pl = t / 96, k = t - pl * 96;
        Cpsh[pl * 97 + k] = g_Cp[(size_t)p0 * H1 + t];
    }
    if (tid < 96) { W3sh[tid] = W3[tid]; b2sh[tid] = b2[tid]; }
    __syncthreads();

    int b  = tid >> 3;   // 0..15
    int pl = tid & 7;    // 0..7
    const float* Ar = Ash + b * 97;
    const float* Cr = Cpsh + pl * 97;

    float s[96];
    #pragma unroll
    for (int j = 0; j < 96; j++) s[j] = b2sh[j];

    #pragma unroll 2
    for (int k = 0; k < 96; k++) {
        float v = gelu_exact(Ar[k] + Cr[k]);
        const float4* w = (const float4*)(W2sh + k * 96);
        #pragma unroll
        for (int j4 = 0; j4 < 24; j4++) {
            float4 a = w[j4];
            s[j4 * 4 + 0] += v * a.x;
            s[j4 * 4 + 1] += v * a.y;
            s[j4 * 4 + 2] += v * a.z;
            s[j4 * 4 + 3] += v * a.w;
        }
    }

    float acc = b3[0];
    #pragma unroll
    for (int j = 0; j < 96; j++) acc += gelu_exact(s[j]) * W3sh[j];

    out[(size_t)b * PP + p0 + pl] = acc;
}

// ---------------------------------------------------------------------------
extern "C" void kernel_launch(void* const* d_in, const int* in_sizes, int n_in,
                              void* d_out, int out_size) {
    const float* g_q = (const float*)d_in[0];
    const float* Phi = (const float*)d_in[1];
    const void*  pin = (const void*)d_in[2];
    const float* rel = (const float*)d_in[3];
    const float* W1  = (const float*)d_in[4];
    const float* b1  = (const float*)d_in[5];
    const float* W2  = (const float*)d_in[6];
    const float* b2  = (const float*)d_in[7];
    const float* W3  = (const float*)d_in[8];
    const float* b3  = (const float*)d_in[9];
    float* out = (float*)d_out;

    kA<<<(BB * H1 + 255) / 256, 256>>>(g_q, W1, b1);
    kB<<<PP / TPB, 256>>>(Phi, pin, rel, W1);
    kC<<<PP / CPAIRS, 128>>>(W2, b2, W3, b3, out);
}

// round 6
// speedup vs baseline: 1.1183x; 1.1183x over previous
#include <cuda_runtime.h>
#include <math.h>

#define BB 16
#define PP 16384
#define MM 2048
#define D_Z 512
#define D_PHI 256
#define D_R 64
#define H1 96
#define H2 96

// scratch (no allocation allowed)
__device__ float g_A[BB * H1];
__device__ float g_Cp[PP * H1];

__device__ __forceinline__ float gelu_exact(float x) {
    return 0.5f * x * (1.0f + erff(x * 0.70710678118654752440f));
}

// ---- packed f32x2 helpers (sm_100+) ----
__device__ __forceinline__ unsigned long long pack2(float x, float y) {
    unsigned long long r;
    asm("mov.b64 %0, {%1, %2};" : "=l"(r) : "f"(x), "f"(y));
    return r;
}
__device__ __forceinline__ unsigned long long fma2(unsigned long long a,
                                                   unsigned long long b,
                                                   unsigned long long c) {
    unsigned long long d;
    asm("fma.rn.f32x2 %0, %1, %2, %3;" : "=l"(d) : "l"(a), "l"(b), "l"(c));
    return d;
}
__device__ __forceinline__ float2 unpack2(unsigned long long v) {
    float x, y;
    asm("mov.b64 {%0, %1}, %2;" : "=f"(x), "=f"(y) : "l"(v));
    return make_float2(x, y);
}

// ---------------------------------------------------------------------------
// Kernel A: A[b,j] = b1[j] + sum_k g_q[b,k] * W1[k,j]
// 16 blocks (one per b) x 384 threads (4 k-slices x 96 j). Coalesced W1 reads
// across j; g_q staged in smem; split-K reduced through smem.
// ---------------------------------------------------------------------------
__global__ void __launch_bounds__(384) kA(const float* __restrict__ g_q,
                                          const float* __restrict__ W1,
                                          const float* __restrict__ b1) {
    __shared__ float gq_sh[D_Z];
    __shared__ float psum[3 * 96];

    int b = blockIdx.x;
    int tid = threadIdx.x;

    for (int t = tid; t < D_Z; t += 384) gq_sh[t] = g_q[b * D_Z + t];
    __syncthreads();

    int ks = tid / 96;   // 0..3
    int j  = tid % 96;

    float s = 0.f;
    const float* w = W1 + (size_t)(ks * 128) * H1 + j;
    #pragma unroll 8
    for (int k = 0; k < 128; k++)
        s += gq_sh[ks * 128 + k] * w[(size_t)k * H1];

    if (ks > 0) psum[(ks - 1) * 96 + j] = s;
    __syncthreads();
    if (ks == 0) {
        s += psum[j] + psum[96 + j] + psum[192 + j] + b1[j];
        g_A[b * H1 + j] = s;
    }
}

// ---------------------------------------------------------------------------
// Kernel B: Cp[p,j] = sum_k' feat(p,k') * W1[512+k', j]
// feat: k'<256 sum; <512 absdiff; <768 prod; <832 relation.
// pair_index dtype detected on-device (int32 vs int64).
// 64 pairs/block, 256 threads, thread = (pg 0..31, jg 0..7) owns pairs
// {pg, pg+32} x 12 j. K in 13 chunks of 64. Inner loop uses packed f32x2.
// ---------------------------------------------------------------------------
#define TPB 64
#define FS_STRIDE 68

__global__ void __launch_bounds__(256) kB(const float* __restrict__ Phi,
                                          const void* __restrict__ pair_index,
                                          const float* __restrict__ rel,
                                          const float* __restrict__ W1) {
    __shared__ float Fs[TPB * FS_STRIDE];   // feature chunk, padded
    __shared__ float Wc[64 * 96];           // weight chunk
    __shared__ int   pi_sh[TPB * 2];

    int tid = threadIdx.x;
    int p0 = blockIdx.x * TPB;

    // ---- dtype detection + index load ----
    {
        const int* p32 = (const int*)pair_index;
        int w = 0;
        if (tid < TPB * 2) w = p32[(size_t)p0 * 2 + tid];
        int any_odd = __syncthreads_or((tid & 1) ? w : 0);
        if (tid < TPB * 2) {
            int v;
            if (any_odd != 0) {
                v = w;
            } else {
                const long long* p64 = (const long long*)pair_index;
                v = (int)p64[(size_t)p0 * 2 + tid];
            }
            v = v < 0 ? 0 : (v >= MM ? MM - 1 : v);
            pi_sh[tid] = v;
        }
    }

    int jg = tid & 7;
    int pg = tid >> 3;

    unsigned long long a0[6], a1[6];
    #pragma unroll
    for (int i = 0; i < 6; i++) { a0[i] = pack2(0.f, 0.f); a1[i] = a0[i]; }

    for (int kc = 0; kc < 13; kc++) {
        int mode  = kc >> 2;
        int cbase = (kc & 3) * 64;
        __syncthreads();
        for (int t = tid; t < TPB * 64; t += 256) {
            int pp = t >> 6, kk = t & 63;
            float f;
            if (mode == 3) {
                f = rel[(size_t)(p0 + pp) * D_R + kk];
            } else {
                int i0 = pi_sh[pp * 2];
                int j0 = pi_sh[pp * 2 + 1];
                float a = Phi[i0 * D_PHI + cbase + kk];
                float c = Phi[j0 * D_PHI + cbase + kk];
                f = (mode == 0) ? (a + c) : (mode == 1) ? fabsf(a - c) : (a * c);
            }
            Fs[pp * FS_STRIDE + kk] = f;
        }
        for (int t = tid; t < 64 * 24; t += 256) {
            int kk = t / 24, c4 = t % 24;
            ((float4*)Wc)[kk * 24 + c4] =
                ((const float4*)(W1 + (size_t)(D_Z + kc * 64 + kk) * H1))[c4];
        }
        __syncthreads();

        #pragma unroll 4
        for (int kk = 0; kk < 64; kk++) {
            float f0 = Fs[pg * FS_STRIDE + kk];
            float f1 = Fs[(pg + 32) * FS_STRIDE + kk];
            unsigned long long ff0 = pack2(f0, f0);
            unsigned long long ff1 = pack2(f1, f1);
            const ulonglong2* w = (const ulonglong2*)(Wc + kk * 96 + jg * 12);
            ulonglong2 w0 = w[0], w1 = w[1], w2 = w[2];
            a0[0] = fma2(ff0, w0.x, a0[0]); a1[0] = fma2(ff1, w0.x, a1[0]);
            a0[1] = fma2(ff0, w0.y, a0[1]); a1[1] = fma2(ff1, w0.y, a1[1]);
            a0[2] = fma2(ff0, w1.x, a0[2]); a1[2] = fma2(ff1, w1.x, a1[2]);
            a0[3] = fma2(ff0, w1.y, a0[3]); a1[3] = fma2(ff1, w1.y, a1[3]);
            a0[4] = fma2(ff0, w2.x, a0[4]); a1[4] = fma2(ff1, w2.x, a1[4]);
            a0[5] = fma2(ff0, w2.y, a0[5]); a1[5] = fma2(ff1, w2.y, a1[5]);
        }
    }

    {
        ulonglong2* o0 = (ulonglong2*)(g_Cp + (size_t)(p0 + pg) * H1 + jg * 12);
        ulonglong2* o1 = (ulonglong2*)(g_Cp + (size_t)(p0 + pg + 32) * H1 + jg * 12);
        o0[0] = make_ulonglong2(a0[0], a0[1]);
        o0[1] = make_ulonglong2(a0[2], a0[3]);
        o0[2] = make_ulonglong2(a0[4], a0[5]);
        o1[0] = make_ulonglong2(a1[0], a1[1]);
        o1[1] = make_ulonglong2(a1[2], a1[3]);
        o1[2] = make_ulonglong2(a1[4], a1[5]);
    }
}

// ---------------------------------------------------------------------------
// Kernel C: out[b,p] = gelu(gelu(A[b]+Cp[p]) @ W2 + b2) @ W3 + b3
// Block: 8 pairs x 16 b = 128 rows, one thread per row.
// 48 packed f32x2 accumulators in registers; stream k over h1:
//   v = gelu(A[b,k]+Cp[p,k]);  s2[j2] = fma2((v,v), W2row[j2], s2[j2])
// ---------------------------------------------------------------------------
#define CPAIRS 8

__global__ void __launch_bounds__(128) kC(const float* __restrict__ W2,
                                          const float* __restrict__ b2,
                                          const float* __restrict__ W3,
                                          const float* __restrict__ b3,
                                          float* __restrict__ out) {
    __shared__ float W2sh[96 * 96];
    __shared__ float Ash[16 * 97];
    __shared__ float Cpsh[CPAIRS * 97];
    __shared__ float W3sh[96];
    __shared__ float b2sh[96];

    int tid = threadIdx.x;
    int p0 = blockIdx.x * CPAIRS;

    for (int t = tid; t < 2304; t += 128)
        ((float4*)W2sh)[t] = ((const float4*)W2)[t];
    for (int t = tid; t < BB * H1; t += 128) {
        int b = t / 96, k = t - b * 96;
        Ash[b * 97 + k] = g_A[t];
    }
    for (int t = tid; t < CPAIRS * H1; t += 128) {
        int pl = t / 96, k = t - pl * 96;
        Cpsh[pl * 97 + k] = g_Cp[(size_t)p0 * H1 + t];
    }
    if (tid < 96) { W3sh[tid] = W3[tid]; b2sh[tid] = b2[tid]; }
    __syncthreads();

    int b  = tid >> 3;   // 0..15
    int pl = tid & 7;    // 0..7
    const float* Ar = Ash + b * 97;
    const float* Cr = Cpsh + pl * 97;

    unsigned long long s2[48];
    #pragma unroll
    for (int j2 = 0; j2 < 48; j2++) s2[j2] = pack2(b2sh[2 * j2], b2sh[2 * j2 + 1]);

    #pragma unroll 2
    for (int k = 0; k < 96; k++) {
        float v = gelu_exact(Ar[k] + Cr[k]);
        unsigned long long vv = pack2(v, v);
        const ulonglong2* w = (const ulonglong2*)(W2sh + k * 96);
        #pragma unroll
        for (int j4 = 0; j4 < 24; j4++) {
            ulonglong2 ww = w[j4];
            s2[2 * j4 + 0] = fma2(vv, ww.x, s2[2 * j4 + 0]);
            s2[2 * j4 + 1] = fma2(vv, ww.y, s2[2 * j4 + 1]);
        }
    }

    float acc = b3[0];
    #pragma unroll
    for (int j2 = 0; j2 < 48; j2++) {
        float2 sv = unpack2(s2[j2]);
        acc += gelu_exact(sv.x) * W3sh[2 * j2 + 0];
        acc += gelu_exact(sv.y) * W3sh[2 * j2 + 1];
    }

    out[(size_t)b * PP + p0 + pl] = acc;
}

// ---------------------------------------------------------------------------
extern "C" void kernel_launch(void* const* d_in, const int* in_sizes, int n_in,
                              void* d_out, int out_size) {
    const float* g_q = (const float*)d_in[0];
    const float* Phi = (const float*)d_in[1];
    const void*  pin = (const void*)d_in[2];
    const float* rel = (const float*)d_in[3];
    const float* W1  = (const float*)d_in[4];
    const float* b1  = (const float*)d_in[5];
    const float* W2  = (const float*)d_in[6];
    const float* b2  = (const float*)d_in[7];
    const float* W3  = (const float*)d_in[8];
    const float* b3  = (const float*)d_in[9];
    float* out = (float*)d_out;

    kA<<<BB, 384>>>(g_q, W1, b1);
    kB<<<PP / TPB, 256>>>(Phi, pin, rel, W1);
    kC<<<PP / CPAIRS, 128>>>(W2, b2, W3, b3, out);
}

// round 7
// speedup vs baseline: 1.1865x; 1.0610x over previous
#include <cuda_runtime.h>
#include <math.h>

#define BB 16
#define PP 16384
#define MM 2048
#define D_Z 512
#define D_PHI 256
#define D_R 64
#define H1 96
#define H2 96

// scratch (no allocation allowed)
__device__ float g_A[BB * H1];
__device__ float g_Cp[PP * H1];

__device__ __forceinline__ float gelu_exact(float x) {
    return 0.5f * x * (1.0f + erff(x * 0.70710678118654752440f));
}

// ---- packed f32x2 helpers (sm_100+) ----
__device__ __forceinline__ unsigned long long pack2(float x, float y) {
    unsigned long long r;
    asm("mov.b64 %0, {%1, %2};" : "=l"(r) : "f"(x), "f"(y));
    return r;
}
__device__ __forceinline__ unsigned long long fma2(unsigned long long a,
                                                   unsigned long long b,
                                                   unsigned long long c) {
    unsigned long long d;
    asm("fma.rn.f32x2 %0, %1, %2, %3;" : "=l"(d) : "l"(a), "l"(b), "l"(c));
    return d;
}
__device__ __forceinline__ float2 unpack2(unsigned long long v) {
    float x, y;
    asm("mov.b64 {%0, %1}, %2;" : "=f"(x), "=f"(y) : "l"(v));
    return make_float2(x, y);
}

// ---------------------------------------------------------------------------
// Kernel A: A[b,j] = b1[j] + sum_k g_q[b,k] * W1[k,j]
// 16 blocks (one per b) x 768 threads (8 k-slices x 96 j), smem split-K reduce.
// ---------------------------------------------------------------------------
__global__ void __launch_bounds__(768) kA(const float* __restrict__ g_q,
                                          const float* __restrict__ W1,
                                          const float* __restrict__ b1) {
    __shared__ float gq_sh[D_Z];
    __shared__ float psum[7 * 96];

    int b = blockIdx.x;
    int tid = threadIdx.x;

    for (int t = tid; t < D_Z; t += 768) gq_sh[t] = g_q[b * D_Z + t];
    __syncthreads();

    int ks = tid / 96;   // 0..7
    int j  = tid % 96;

    float s = 0.f;
    const float* w = W1 + (size_t)(ks * 64) * H1 + j;
    #pragma unroll 8
    for (int k = 0; k < 64; k++)
        s += gq_sh[ks * 64 + k] * w[(size_t)k * H1];

    if (ks > 0) psum[(ks - 1) * 96 + j] = s;
    __syncthreads();
    if (ks == 0) {
        #pragma unroll
        for (int i = 0; i < 7; i++) s += psum[i * 96 + j];
        g_A[b * H1 + j] = s + b1[j];
    }
}

// ---------------------------------------------------------------------------
// Kernel B: Cp[p,j] = sum_k' feat(p,k') * W1[512+k', j]
// feat: k'<256 sum; <512 absdiff; <768 prod; <832 relation.
// pair_index dtype detected on-device (int32 vs int64).
// 64 pairs/block, 256 threads, thread = (pg 0..31, jg 0..7) owns pairs
// {pg, pg+32} x 12 j. K in 13 chunks of 64. Packed f32x2 inner loop.
// ---------------------------------------------------------------------------
#define TPB 64
#define FS_STRIDE 68

__global__ void __launch_bounds__(256) kB(const float* __restrict__ Phi,
                                          const void* __restrict__ pair_index,
                                          const float* __restrict__ rel,
                                          const float* __restrict__ W1) {
    __shared__ float Fs[TPB * FS_STRIDE];   // feature chunk, padded
    __shared__ float Wc[64 * 96];           // weight chunk
    __shared__ int   pi_sh[TPB * 2];

    int tid = threadIdx.x;
    int p0 = blockIdx.x * TPB;

    // ---- dtype detection + index load ----
    {
        const int* p32 = (const int*)pair_index;
        int w = 0;
        if (tid < TPB * 2) w = p32[(size_t)p0 * 2 + tid];
        int any_odd = __syncthreads_or((tid & 1) ? w : 0);
        if (tid < TPB * 2) {
            int v;
            if (any_odd != 0) {
                v = w;
            } else {
                const long long* p64 = (const long long*)pair_index;
                v = (int)p64[(size_t)p0 * 2 + tid];
            }
            v = v < 0 ? 0 : (v >= MM ? MM - 1 : v);
            pi_sh[tid] = v;
        }
    }

    int jg = tid & 7;
    int pg = tid >> 3;

    unsigned long long a0[6], a1[6];
    #pragma unroll
    for (int i = 0; i < 6; i++) { a0[i] = pack2(0.f, 0.f); a1[i] = a0[i]; }

    for (int kc = 0; kc < 13; kc++) {
        int mode  = kc >> 2;
        int cbase = (kc & 3) * 64;
        __syncthreads();
        for (int t = tid; t < TPB * 64; t += 256) {
            int pp = t >> 6, kk = t & 63;
            float f;
            if (mode == 3) {
                f = rel[(size_t)(p0 + pp) * D_R + kk];
            } else {
                int i0 = pi_sh[pp * 2];
                int j0 = pi_sh[pp * 2 + 1];
                float a = Phi[i0 * D_PHI + cbase + kk];
                float c = Phi[j0 * D_PHI + cbase + kk];
                f = (mode == 0) ? (a + c) : (mode == 1) ? fabsf(a - c) : (a * c);
            }
            Fs[pp * FS_STRIDE + kk] = f;
        }
        for (int t = tid; t < 64 * 24; t += 256) {
            int kk = t / 24, c4 = t % 24;
            ((float4*)Wc)[kk * 24 + c4] =
                ((const float4*)(W1 + (size_t)(D_Z + kc * 64 + kk) * H1))[c4];
        }
        __syncthreads();

        #pragma unroll 4
        for (int kk = 0; kk < 64; kk++) {
            float f0 = Fs[pg * FS_STRIDE + kk];
            float f1 = Fs[(pg + 32) * FS_STRIDE + kk];
            unsigned long long ff0 = pack2(f0, f0);
            unsigned long long ff1 = pack2(f1, f1);
            const ulonglong2* w = (const ulonglong2*)(Wc + kk * 96 + jg * 12);
            ulonglong2 w0 = w[0], w1 = w[1], w2 = w[2];
            a0[0] = fma2(ff0, w0.x, a0[0]); a1[0] = fma2(ff1, w0.x, a1[0]);
            a0[1] = fma2(ff0, w0.y, a0[1]); a1[1] = fma2(ff1, w0.y, a1[1]);
            a0[2] = fma2(ff0, w1.x, a0[2]); a1[2] = fma2(ff1, w1.x, a1[2]);
            a0[3] = fma2(ff0, w1.y, a0[3]); a1[3] = fma2(ff1, w1.y, a1[3]);
            a0[4] = fma2(ff0, w2.x, a0[4]); a1[4] = fma2(ff1, w2.x, a1[4]);
            a0[5] = fma2(ff0, w2.y, a0[5]); a1[5] = fma2(ff1, w2.y, a1[5]);
        }
    }

    {
        ulonglong2* o0 = (ulonglong2*)(g_Cp + (size_t)(p0 + pg) * H1 + jg * 12);
        ulonglong2* o1 = (ulonglong2*)(g_Cp + (size_t)(p0 + pg + 32) * H1 + jg * 12);
        o0[0] = make_ulonglong2(a0[0], a0[1]);
        o0[1] = make_ulonglong2(a0[2], a0[3]);
        o0[2] = make_ulonglong2(a0[4], a0[5]);
        o1[0] = make_ulonglong2(a1[0], a1[1]);
        o1[1] = make_ulonglong2(a1[2], a1[3]);
        o1[2] = make_ulonglong2(a1[4], a1[5]);
    }
}

// ---------------------------------------------------------------------------
// Kernel C (register-tiled GEMM): out[b,p] = gelu(gelu(A[b]+Cp[p])@W2+b2)@W3+b3
// 128 rows (16 b x 8 pairs) per block, 256 threads.
// Phase 1: stage h1[k][row] = gelu(A+Cp) in smem (transposed, conflict-free).
// Phase 2: thread (jg=tid>>5, rg=tid&31) owns rows {rg,+32,+64,+96} x 12 j:
//          24 f32x2 accumulators, per-k = 4 LDS + 3 broadcast LDS.128 + 24 FFMA2.
// Phase 3: gelu + W3 contraction, cross-jg reduction via smem.
// Dynamic smem ~98 KB (2 blocks/SM).
// ---------------------------------------------------------------------------
#define CPAIRS 8
#define CROWS 128
#define KC_SMEM_FLOATS (9216 + 96 * 128 + 16 * 97 + CPAIRS * 97 + 96 + 96 + 8 * 128)

__global__ void __launch_bounds__(256) kC(const float* __restrict__ W2,
                                          const float* __restrict__ b2,
                                          const float* __restrict__ W3,
                                          const float* __restrict__ b3,
                                          float* __restrict__ out) {
    extern __shared__ float sm[];
    float* W2sh = sm;                        // 9216
    float* h1sh = W2sh + 9216;               // 96*128 = 12288, layout [k][row]
    float* Ash  = h1sh + 96 * 128;           // 16*97
    float* Cpsh = Ash + 16 * 97;             // 8*97
    float* W3sh = Cpsh + CPAIRS * 97;        // 96
    float* b2sh = W3sh + 96;                 // 96
    float* psum = b2sh + 96;                 // 8*128

    int tid = threadIdx.x;
    int p0 = blockIdx.x * CPAIRS;

    for (int t = tid; t < 2304; t += 256)
        ((float4*)W2sh)[t] = ((const float4*)W2)[t];
    for (int t = tid; t < BB * H1; t += 256) {
        int b = t / 96, k = t - b * 96;
        Ash[b * 97 + k] = g_A[t];
    }
    for (int t = tid; t < CPAIRS * H1; t += 256) {
        int pl = t / 96, k = t - pl * 96;
        Cpsh[pl * 97 + k] = g_Cp[(size_t)p0 * H1 + t];
    }
    if (tid < 96) { W3sh[tid] = W3[tid]; b2sh[tid] = b2[tid]; }
    __syncthreads();

    // Phase 1: h1sh[k][row] = gelu(A[b][k] + Cp[pl][k]), row = b*8 + pl
    for (int idx = tid; idx < 96 * CROWS; idx += 256) {
        int row = idx & 127;
        int k   = idx >> 7;
        int b   = row >> 3;
        int pl  = row & 7;
        h1sh[k * CROWS + row] = gelu_exact(Ash[b * 97 + k] + Cpsh[pl * 97 + k]);
    }
    __syncthreads();

    // Phase 2: register-tiled GEMM h1[128x96] @ W2[96x96]
    int jg = tid >> 5;   // 0..7 -> cols jg*12 .. jg*12+11
    int rg = tid & 31;   // rows rg, rg+32, rg+64, rg+96

    unsigned long long acc[4][6];
    #pragma unroll
    for (int r = 0; r < 4; r++) {
        acc[r][0] = pack2(b2sh[jg * 12 + 0],  b2sh[jg * 12 + 1]);
        acc[r][1] = pack2(b2sh[jg * 12 + 2],  b2sh[jg * 12 + 3]);
        acc[r][2] = pack2(b2sh[jg * 12 + 4],  b2sh[jg * 12 + 5]);
        acc[r][3] = pack2(b2sh[jg * 12 + 6],  b2sh[jg * 12 + 7]);
        acc[r][4] = pack2(b2sh[jg * 12 + 8],  b2sh[jg * 12 + 9]);
        acc[r][5] = pack2(b2sh[jg * 12 + 10], b2sh[jg * 12 + 11]);
    }

    #pragma unroll 2
    for (int k = 0; k < 96; k++) {
        const float* hrow = h1sh + k * CROWS + rg;
        unsigned long long h0 = pack2(hrow[0],  hrow[0]);
        unsigned long long h1v = pack2(hrow[32], hrow[32]);
        unsigned long long h2v = pack2(hrow[64], hrow[64]);
        unsigned long long h3v = pack2(hrow[96], hrow[96]);
        const ulonglong2* w = (const ulonglong2*)(W2sh + k * 96 + jg * 12);
        ulonglong2 w0 = w[0], w1 = w[1], w2 = w[2];
        acc[0][0] = fma2(h0, w0.x, acc[0][0]);
        acc[0][1] = fma2(h0, w0.y, acc[0][1]);
        acc[0][2] = fma2(h0, w1.x, acc[0][2]);
        acc[0][3] = fma2(h0, w1.y, acc[0][3]);
        acc[0][4] = fma2(h0, w2.x, acc[0][4]);
        acc[0][5] = fma2(h0, w2.y, acc[0][5]);
        acc[1][0] = fma2(h1v, w0.x, acc[1][0]);
        acc[1][1] = fma2(h1v, w0.y, acc[1][1]);
        acc[1][2] = fma2(h1v, w1.x, acc[1][2]);
        acc[1][3] = fma2(h1v, w1.y, acc[1][3]);
        acc[1][4] = fma2(h1v, w2.x, acc[1][4]);
        acc[1][5] = fma2(h1v, w2.y, acc[1][5]);
        acc[2][0] = fma2(h2v, w0.x, acc[2][0]);
        acc[2][1] = fma2(h2v, w0.y, acc[2][1]);
        acc[2][2] = fma2(h2v, w1.x, acc[2][2]);
        acc[2][3] = fma2(h2v, w1.y, acc[2][3]);
        acc[2][4] = fma2(h2v, w2.x, acc[2][4]);
        acc[2][5] = fma2(h2v, w2.y, acc[2][5]);
        acc[3][0] = fma2(h3v, w0.x, acc[3][0]);
        acc[3][1] = fma2(h3v, w0.y, acc[3][1]);
        acc[3][2] = fma2(h3v, w1.x, acc[3][2]);
        acc[3][3] = fma2(h3v, w1.y, acc[3][3]);
        acc[3][4] = fma2(h3v, w2.x, acc[3][4]);
        acc[3][5] = fma2(h3v, w2.y, acc[3][5]);
    }

    // Phase 3: gelu + W3 partial contraction per thread, reduce across jg
    float w3r[12];
    #pragma unroll
    for (int j = 0; j < 12; j++) w3r[j] = W3sh[jg * 12 + j];

    #pragma unroll
    for (int r = 0; r < 4; r++) {
        float part = 0.f;
        #pragma unroll
        for (int j2 = 0; j2 < 6; j2++) {
            float2 sv = unpack2(acc[r][j2]);
            part += gelu_exact(sv.x) * w3r[2 * j2 + 0];
            part += gelu_exact(sv.y) * w3r[2 * j2 + 1];
        }
        psum[jg * CROWS + rg + r * 32] = part;
    }
    __syncthreads();

    if (tid < CROWS) {
        int row = tid;
        float s = b3[0];
        #pragma unroll
        for (int g = 0; g < 8; g++) s += psum[g * CROWS + row];
        int b  = row >> 3;
        int pl = row & 7;
        out[(size_t)b * PP + p0 + pl] = s;
    }
}

// ---------------------------------------------------------------------------
extern "C" void kernel_launch(void* const* d_in, const int* in_sizes, int n_in,
                              void* d_out, int out_size) {
    const float* g_q = (const float*)d_in[0];
    const float* Phi = (const float*)d_in[1];
    const void*  pin = (const void*)d_in[2];
    const float* rel = (const float*)d_in[3];
    const float* W1  = (const float*)d_in[4];
    const float* b1  = (const float*)d_in[5];
    const float* W2  = (const float*)d_in[6];
    const float* b2  = (const float*)d_in[7];
    const float* W3  = (const float*)d_in[8];
    const float* b3  = (const float*)d_in[9];
    float* out = (float*)d_out;

    cudaFuncSetAttribute(kC, cudaFuncAttributeMaxDynamicSharedMemorySize,
                         KC_SMEM_FLOATS * 4);

    kA<<<BB, 768>>>(g_q, W1, b1);
    kB<<<PP / TPB, 256>>>(Phi, pin, rel, W1);
    kC<<<PP / CPAIRS, 256, KC_SMEM_FLOATS * 4>>>(W2, b2, W3, b3, out);
}

// round 9
// speedup vs baseline: 1.5122x; 1.2745x over previous
#include <cuda_runtime.h>
#include <cuda_bf16.h>
#include <math.h>
#include <stdint.h>

#define BB 16
#define PP 16384
#define MM 2048
#define D_Z 512
#define D_PHI 256
#define D_R 64
#define H1 96
#define H2 96

// scratch (no allocation allowed)
__device__ float g_A[BB * H1];
__device__ float g_Cp[PP * H1];

__device__ __forceinline__ float gelu_exact(float x) {
    return 0.5f * x * (1.0f + erff(x * 0.70710678118654752440f));
}

// ---- packed f32x2 helpers (used by kB) ----
__device__ __forceinline__ unsigned long long pack2(float x, float y) {
    unsigned long long r;
    asm("mov.b64 %0, {%1, %2};" : "=l"(r) : "f"(x), "f"(y));
    return r;
}
__device__ __forceinline__ unsigned long long fma2(unsigned long long a,
                                                   unsigned long long b,
                                                   unsigned long long c) {
    unsigned long long d;
    asm("fma.rn.f32x2 %0, %1, %2, %3;" : "=l"(d) : "l"(a), "l"(b), "l"(c));
    return d;
}

// ---- bf16 split helpers ----
__device__ __forceinline__ void bf16split(float x, unsigned short& h, unsigned short& l) {
    __nv_bfloat16 bh = __float2bfloat16_rn(x);
    float fh = __bfloat162float(bh);
    __nv_bfloat16 bl = __float2bfloat16_rn(x - fh);
    h = __bfloat16_as_ushort(bh);
    l = __bfloat16_as_ushort(bl);
}
__device__ __forceinline__ uint32_t packu(unsigned short lo16, unsigned short hi16) {
    return (uint32_t)lo16 | ((uint32_t)hi16 << 16);
}

// bf16 mma.sync (sm_80+ baseline, legal on compute_100)
__device__ __forceinline__ void mma_bf16(float* c,
                                         uint32_t a0, uint32_t a1, uint32_t a2, uint32_t a3,
                                         uint32_t b0, uint32_t b1) {
    asm volatile(
        "mma.sync.aligned.m16n8k16.row.col.f32.bf16.bf16.f32 "
        "{%0,%1,%2,%3}, {%4,%5,%6,%7}, {%8,%9}, {%0,%1,%2,%3};"
        : "+f"(c[0]), "+f"(c[1]), "+f"(c[2]), "+f"(c[3])
        : "r"(a0), "r"(a1), "r"(a2), "r"(a3), "r"(b0), "r"(b1));
}

// ---------------------------------------------------------------------------
// Kernel A: A[b,j] = b1[j] + sum_k g_q[b,k] * W1[k,j]
// ---------------------------------------------------------------------------
__global__ void __launch_bounds__(768) kA(const float* __restrict__ g_q,
                                          const float* __restrict__ W1,
                                          const float* __restrict__ b1) {
    __shared__ float gq_sh[D_Z];
    __shared__ float psum[7 * 96];
    int b = blockIdx.x;
    int tid = threadIdx.x;
    for (int t = tid; t < D_Z; t += 768) gq_sh[t] = g_q[b * D_Z + t];
    __syncthreads();
    int ks = tid / 96, j = tid % 96;
    float s = 0.f;
    const float* w = W1 + (size_t)(ks * 64) * H1 + j;
    #pragma unroll 8
    for (int k = 0; k < 64; k++)
        s += gq_sh[ks * 64 + k] * w[(size_t)k * H1];
    if (ks > 0) psum[(ks - 1) * 96 + j] = s;
    __syncthreads();
    if (ks == 0) {
        #pragma unroll
        for (int i = 0; i < 7; i++) s += psum[i * 96 + j];
        g_A[b * H1 + j] = s + b1[j];
    }
}

// ---------------------------------------------------------------------------
// Kernel B: Cp[p,j] = sum_k' feat(p,k') * W1[512+k', j]   (unchanged)
// ---------------------------------------------------------------------------
#define TPB 64
#define FS_STRIDE 68

__global__ void __launch_bounds__(256) kB(const float* __restrict__ Phi,
                                          const void* __restrict__ pair_index,
                                          const float* __restrict__ rel,
                                          const float* __restrict__ W1) {
    __shared__ float Fs[TPB * FS_STRIDE];
    __shared__ float Wc[64 * 96];
    __shared__ int   pi_sh[TPB * 2];

    int tid = threadIdx.x;
    int p0 = blockIdx.x * TPB;
    {
        const int* p32 = (const int*)pair_index;
        int w = 0;
        if (tid < TPB * 2) w = p32[(size_t)p0 * 2 + tid];
        int any_odd = __syncthreads_or((tid & 1) ? w : 0);
        if (tid < TPB * 2) {
            int v;
            if (any_odd != 0) v = w;
            else {
                const long long* p64 = (const long long*)pair_index;
                v = (int)p64[(size_t)p0 * 2 + tid];
            }
            v = v < 0 ? 0 : (v >= MM ? MM - 1 : v);
            pi_sh[tid] = v;
        }
    }
    int jg = tid & 7;
    int pg = tid >> 3;
    unsigned long long a0[6], a1[6];
    #pragma unroll
    for (int i = 0; i < 6; i++) { a0[i] = pack2(0.f, 0.f); a1[i] = a0[i]; }
    for (int kc = 0; kc < 13; kc++) {
        int mode  = kc >> 2;
        int cbase = (kc & 3) * 64;
        __syncthreads();
        for (int t = tid; t < TPB * 64; t += 256) {
            int pp = t >> 6, kk = t & 63;
            float f;
            if (mode == 3) {
                f = rel[(size_t)(p0 + pp) * D_R + kk];
            } else {
                int i0 = pi_sh[pp * 2];
                int j0 = pi_sh[pp * 2 + 1];
                float a = Phi[i0 * D_PHI + cbase + kk];
                float c = Phi[j0 * D_PHI + cbase + kk];
                f = (mode == 0) ? (a + c) : (mode == 1) ? fabsf(a - c) : (a * c);
            }
            Fs[pp * FS_STRIDE + kk] = f;
        }
        for (int t = tid; t < 64 * 24; t += 256) {
            int kk = t / 24, c4 = t % 24;
            ((float4*)Wc)[kk * 24 + c4] =
                ((const float4*)(W1 + (size_t)(D_Z + kc * 64 + kk) * H1))[c4];
        }
        __syncthreads();
        #pragma unroll 4
        for (int kk = 0; kk < 64; kk++) {
            float f0 = Fs[pg * FS_STRIDE + kk];
            float f1 = Fs[(pg + 32) * FS_STRIDE + kk];
            unsigned long long ff0 = pack2(f0, f0);
            unsigned long long ff1 = pack2(f1, f1);
            const ulonglong2* w = (const ulonglong2*)(Wc + kk * 96 + jg * 12);
            ulonglong2 w0 = w[0], w1 = w[1], w2 = w[2];
            a0[0] = fma2(ff0, w0.x, a0[0]); a1[0] = fma2(ff1, w0.x, a1[0]);
            a0[1] = fma2(ff0, w0.y, a0[1]); a1[1] = fma2(ff1, w0.y, a1[1]);
            a0[2] = fma2(ff0, w1.x, a0[2]); a1[2] = fma2(ff1, w1.x, a1[2]);
            a0[3] = fma2(ff0, w1.y, a0[3]); a1[3] = fma2(ff1, w1.y, a1[3]);
            a0[4] = fma2(ff0, w2.x, a0[4]); a1[4] = fma2(ff1, w2.x, a1[4]);
            a0[5] = fma2(ff0, w2.y, a0[5]); a1[5] = fma2(ff1, w2.y, a1[5]);
        }
    }
    ulonglong2* o0 = (ulonglong2*)(g_Cp + (size_t)(p0 + pg) * H1 + jg * 12);
    ulonglong2* o1 = (ulonglong2*)(g_Cp + (size_t)(p0 + pg + 32) * H1 + jg * 12);
    o0[0] = make_ulonglong2(a0[0], a0[1]);
    o0[1] = make_ulonglong2(a0[2], a0[3]);
    o0[2] = make_ulonglong2(a0[4], a0[5]);
    o1[0] = make_ulonglong2(a1[0], a1[1]);
    o1[1] = make_ulonglong2(a1[2], a1[3]);
    o1[2] = make_ulonglong2(a1[4], a1[5]);
}

// ---------------------------------------------------------------------------
// Kernel C (mma.sync bf16 hi/lo): out[b,p] = gelu(gelu(A+Cp)@W2+b2)@W3+b3
// Block = 1 b x 128 p-rows, 256 threads (8 warps).
// Warp tile 32 rows x 48 cols: acc = 2 mtiles x 6 ntiles x 4 = 48 fp32.
// A = h1 bf16 hi/lo in smem [row][k] (stride 52 u32); B = W2^T hi/lo [n][k].
// 3 passes: Ahi*Bhi + Alo*Bhi + Ahi*Blo; bias b2 + gelu + W3-dot in epilogue.
// ---------------------------------------------------------------------------
#define SA_STR 52          // u32 words per row (conflict-free: 52 = 20 mod 32)
#define AHI_OFF 0
#define ALO_OFF 6656       // 128*52
#define BHI_OFF 13312
#define BLO_OFF 18304      // +96*52
#define AF_OFF  23296
#define B2_OFF  23392
#define W3_OFF  23488
#define PS_OFF  23584
#define KC_SMEM_BYTES ((23584 + 256) * 4)

__global__ void __launch_bounds__(256) kC(const float* __restrict__ W2,
                                          const float* __restrict__ b2,
                                          const float* __restrict__ W3,
                                          const float* __restrict__ b3,
                                          float* __restrict__ out) {
    extern __shared__ uint32_t smw[];
    uint32_t* Ahi = smw + AHI_OFF;
    uint32_t* Alo = smw + ALO_OFF;
    uint32_t* Bhi = smw + BHI_OFF;
    uint32_t* Blo = smw + BLO_OFF;
    float* Af  = (float*)(smw + AF_OFF);
    float* b2f = (float*)(smw + B2_OFF);
    float* W3f = (float*)(smw + W3_OFF);
    float* ps  = (float*)(smw + PS_OFF);

    int tid  = threadIdx.x;
    int wid  = tid >> 5;
    int lane = tid & 31;
    int gid  = lane >> 2;
    int tig  = lane & 3;
    int b    = blockIdx.y;
    int p0   = blockIdx.x * 128;

    if (tid < 96) {
        Af[tid]  = g_A[b * H1 + tid];
        b2f[tid] = b2[tid];
        W3f[tid] = W3[tid];
    }
    __syncthreads();

    // ---- W2^T hi/lo into smem [n][k] (ushort writes; reads coalesced) ----
    for (int idx = tid; idx < 96 * 96; idx += 256) {
        int k = idx / 96, n = idx - k * 96;
        unsigned short h, l;
        bf16split(W2[idx], h, l);
        ((unsigned short*)Bhi)[n * (SA_STR * 2) + k] = h;
        ((unsigned short*)Blo)[n * (SA_STR * 2) + k] = l;
    }

    // ---- h1 = gelu(Af + Cp), split, store [row][k] (thread = row x k-half) ----
    {
        int row = tid >> 1, half = tid & 1;
        const float4* cp4 = (const float4*)(g_Cp + (size_t)(p0 + row) * H1) + half * 12;
        uint32_t* ah = Ahi + row * SA_STR + half * 24;
        uint32_t* al = Alo + row * SA_STR + half * 24;
        #pragma unroll
        for (int q = 0; q < 12; q++) {
            float4 v = cp4[q];
            int k = half * 48 + q * 4;
            float g0 = gelu_exact(Af[k + 0] + v.x);
            float g1 = gelu_exact(Af[k + 1] + v.y);
            float g2 = gelu_exact(Af[k + 2] + v.z);
            float g3 = gelu_exact(Af[k + 3] + v.w);
            unsigned short h0, l0, h1v, l1v, h2, l2, h3, l3;
            bf16split(g0, h0, l0); bf16split(g1, h1v, l1v);
            bf16split(g2, h2, l2); bf16split(g3, h3, l3);
            ah[q * 2 + 0] = packu(h0, h1v);
            ah[q * 2 + 1] = packu(h2, h3);
            al[q * 2 + 0] = packu(l0, l1v);
            al[q * 2 + 1] = packu(l2, l3);
        }
    }
    __syncthreads();

    // ---- main loop: 3 passes x 6 k16-steps, warp tile 32x48 ----
    int mrow = (wid >> 1) * 32;
    int ncol = (wid & 1) * 48;

    float c[2][6][4];
    #pragma unroll
    for (int mt = 0; mt < 2; mt++)
        #pragma unroll
        for (int nt = 0; nt < 6; nt++)
            #pragma unroll
            for (int r = 0; r < 4; r++) c[mt][nt][r] = 0.f;

    #pragma unroll 1
    for (int pass = 0; pass < 3; pass++) {
        const uint32_t* Ab = (pass == 1) ? Alo : Ahi;
        const uint32_t* Bb = (pass == 2) ? Blo : Bhi;
        #pragma unroll
        for (int ks = 0; ks < 6; ks++) {
            int kw = ks * 8;
            uint32_t bfr[6][2];
            #pragma unroll
            for (int nt = 0; nt < 6; nt++) {
                int n = ncol + nt * 8 + gid;
                bfr[nt][0] = Bb[n * SA_STR + kw + tig];
                bfr[nt][1] = Bb[n * SA_STR + kw + 4 + tig];
            }
            #pragma unroll
            for (int mt = 0; mt < 2; mt++) {
                int r = mrow + mt * 16 + gid;
                uint32_t a0 = Ab[(r)     * SA_STR + kw + tig];
                uint32_t a1 = Ab[(r + 8) * SA_STR + kw + tig];
                uint32_t a2 = Ab[(r)     * SA_STR + kw + 4 + tig];
                uint32_t a3 = Ab[(r + 8) * SA_STR + kw + 4 + tig];
                #pragma unroll
                for (int nt = 0; nt < 6; nt++)
                    mma_bf16(c[mt][nt], a0, a1, a2, a3, bfr[nt][0], bfr[nt][1]);
            }
        }
    }

    // ---- epilogue: bias + gelu + W3-dot, reduce over tig then col-halves ----
    #pragma unroll
    for (int mt = 0; mt < 2; mt++) {
        #pragma unroll
        for (int rh = 0; rh < 2; rh++) {
            float part = 0.f;
            #pragma unroll
            for (int nt = 0; nt < 6; nt++) {
                int col = ncol + nt * 8 + tig * 2;
                float v0 = c[mt][nt][rh * 2 + 0] + b2f[col];
                float v1 = c[mt][nt][rh * 2 + 1] + b2f[col + 1];
                part += gelu_exact(v0) * W3f[col];
                part += gelu_exact(v1) * W3f[col + 1];
            }
            part += __shfl_xor_sync(0xFFFFFFFF, part, 1);
            part += __shfl_xor_sync(0xFFFFFFFF, part, 2);
            if (tig == 0) {
                int row = mrow + mt * 16 + rh * 8 + gid;
                ps[(wid & 1) * 128 + row] = part;
            }
        }
    }
    __syncthreads();

    if (tid < 128) {
        float s = ps[tid] + ps[128 + tid] + b3[0];
        out[(size_t)b * PP + p0 + tid] = s;
    }
}

// ---------------------------------------------------------------------------
extern "C" void kernel_launch(void* const* d_in, const int* in_sizes, int n_in,
                              void* d_out, int out_size) {
    const float* g_q = (const float*)d_in[0];
    const float* Phi = (const float*)d_in[1];
    const void*  pin = (const void*)d_in[2];
    const float* rel = (const float*)d_in[3];
    const float* W1  = (const float*)d_in[4];
    const float* b1  = (const float*)d_in[5];
    const float* W2  = (const float*)d_in[6];
    const float* b2  = (const float*)d_in[7];
    const float* W3  = (const float*)d_in[8];
    const float* b3  = (const float*)d_in[9];
    float* out = (float*)d_out;

    cudaFuncSetAttribute(kC, cudaFuncAttributeMaxDynamicSharedMemorySize,
                         KC_SMEM_BYTES);

    kA<<<BB, 768>>>(g_q, W1, b1);
    kB<<<PP / TPB, 256>>>(Phi, pin, rel, W1);
    kC<<<dim3(PP / 128, BB), 256, KC_SMEM_BYTES>>>(W2, b2, W3, b3, out);
}

// round 10
// speedup vs baseline: 1.6955x; 1.1212x over previous
#include <cuda_runtime.h>
#include <cuda_bf16.h>
#include <math.h>
#include <stdint.h>

#define BB 16
#define PP 16384
#define MM 2048
#define D_Z 512
#define D_PHI 256
#define D_R 64
#define H1 96
#define H2 96

// scratch (no allocation allowed)
__device__ float g_A[BB * H1];
__device__ float g_Cp[PP * H1];

__device__ __forceinline__ float gelu_exact(float x) {
    return 0.5f * x * (1.0f + erff(x * 0.70710678118654752440f));
}

// ---- bf16 split helpers ----
__device__ __forceinline__ void bf16split(float x, unsigned short& h, unsigned short& l) {
    __nv_bfloat16 bh = __float2bfloat16_rn(x);
    float fh = __bfloat162float(bh);
    __nv_bfloat16 bl = __float2bfloat16_rn(x - fh);
    h = __bfloat16_as_ushort(bh);
    l = __bfloat16_as_ushort(bl);
}
__device__ __forceinline__ uint32_t packu(unsigned short lo16, unsigned short hi16) {
    return (uint32_t)lo16 | ((uint32_t)hi16 << 16);
}

// bf16 mma.sync (sm_80+ baseline, legal on compute_100)
__device__ __forceinline__ void mma_bf16(float* c,
                                         uint32_t a0, uint32_t a1, uint32_t a2, uint32_t a3,
                                         uint32_t b0, uint32_t b1) {
    asm volatile(
        "mma.sync.aligned.m16n8k16.row.col.f32.bf16.bf16.f32 "
        "{%0,%1,%2,%3}, {%4,%5,%6,%7}, {%8,%9}, {%0,%1,%2,%3};"
        : "+f"(c[0]), "+f"(c[1]), "+f"(c[2]), "+f"(c[3])
        : "r"(a0), "r"(a1), "r"(a2), "r"(a3), "r"(b0), "r"(b1));
}

// ---------------------------------------------------------------------------
// Kernel A: A[b,j] = b1[j] + sum_k g_q[b,k] * W1[k,j]
// ---------------------------------------------------------------------------
__global__ void __launch_bounds__(768) kA(const float* __restrict__ g_q,
                                          const float* __restrict__ W1,
                                          const float* __restrict__ b1) {
    __shared__ float gq_sh[D_Z];
    __shared__ float psum[7 * 96];
    int b = blockIdx.x;
    int tid = threadIdx.x;
    for (int t = tid; t < D_Z; t += 768) gq_sh[t] = g_q[b * D_Z + t];
    __syncthreads();
    int ks = tid / 96, j = tid % 96;
    float s = 0.f;
    const float* w = W1 + (size_t)(ks * 64) * H1 + j;
    #pragma unroll 8
    for (int k = 0; k < 64; k++)
        s += gq_sh[ks * 64 + k] * w[(size_t)k * H1];
    if (ks > 0) psum[(ks - 1) * 96 + j] = s;
    __syncthreads();
    if (ks == 0) {
        #pragma unroll
        for (int i = 0; i < 7; i++) s += psum[i * 96 + j];
        g_A[b * H1 + j] = s + b1[j];
    }
}

// ---------------------------------------------------------------------------
// Kernel B (mma.sync bf16 hi/lo): Cp[p,:] = feat(p,:) @ W1[512:,:]
// Block = 128 pairs, 256 threads (8 warps). Warp tile 32 rows x 48 cols.
// K = 832 in 13 chunks of 64. Per chunk: build features fp32 -> split bf16
// hi/lo into smem [row][k] (stride 36 u32, conflict-free); stage W1 chunk
// hi/lo [n][k]; 3 passes x 4 k16-steps x 12 mma.
// feat: k'<256 phi_i+phi_j; <512 |phi_i-phi_j|; <768 phi_i*phi_j; <832 rel.
// ---------------------------------------------------------------------------
#define KB_STR 36
#define KB_AHI 0
#define KB_ALO 4608
#define KB_WHI 9216
#define KB_WLO 12672
#define KB_PI  16128
#define KB_SMEM_BYTES (16384 * 4)

__global__ void __launch_bounds__(256) kB(const float* __restrict__ Phi,
                                          const void* __restrict__ pair_index,
                                          const float* __restrict__ rel,
                                          const float* __restrict__ W1) {
    extern __shared__ uint32_t smw[];
    uint32_t* Ahi = smw + KB_AHI;      // 128 x 36
    uint32_t* Alo = smw + KB_ALO;      // 128 x 36
    uint32_t* Whi = smw + KB_WHI;      // 96 x 36
    uint32_t* Wlo = smw + KB_WLO;      // 96 x 36
    int* pi_sh    = (int*)(smw + KB_PI);

    int tid  = threadIdx.x;
    int wid  = tid >> 5;
    int lane = tid & 31;
    int gid  = lane >> 2;
    int tig  = lane & 3;
    int p0   = blockIdx.x * 128;

    // ---- pair_index dtype detection + load (256 values) ----
    {
        const int* p32 = (const int*)pair_index;
        int w = p32[(size_t)p0 * 2 + tid];
        int any_odd = __syncthreads_or((tid & 1) ? w : 0);
        int v;
        if (any_odd != 0) v = w;
        else {
            const long long* p64 = (const long long*)pair_index;
            v = (int)p64[(size_t)p0 * 2 + tid];
        }
        v = v < 0 ? 0 : (v >= MM ? MM - 1 : v);
        pi_sh[tid] = v;
    }

    int mrow = (wid >> 1) * 32;        // 4 row groups x 32
    int ncol = (wid & 1) * 48;         // 2 col halves x 48

    float c[2][6][4];
    #pragma unroll
    for (int mt = 0; mt < 2; mt++)
        #pragma unroll
        for (int nt = 0; nt < 6; nt++)
            #pragma unroll
            for (int r = 0; r < 4; r++) c[mt][nt][r] = 0.f;

    for (int ch = 0; ch < 13; ch++) {
        int mode  = ch >> 2;           // 0 sum, 1 absdiff, 2 prod, 3 relation
        int cbase = (ch & 3) * 64;
        __syncthreads();

        // build feature chunk (split bf16 hi/lo), 2 k per thread-step
        #pragma unroll 4
        for (int idx = tid; idx < 128 * 32; idx += 256) {
            int pp  = idx >> 5;
            int kk2 = idx & 31;
            float f0, f1;
            if (mode == 3) {
                const float* rp = rel + (size_t)(p0 + pp) * D_R + kk2 * 2;
                f0 = rp[0]; f1 = rp[1];
            } else {
                int i0 = pi_sh[pp * 2];
                int j0 = pi_sh[pp * 2 + 1];
                const float* pi_ = Phi + (size_t)i0 * D_PHI + cbase + kk2 * 2;
                const float* pj_ = Phi + (size_t)j0 * D_PHI + cbase + kk2 * 2;
                float a0v = pi_[0], a1v = pi_[1];
                float c0v = pj_[0], c1v = pj_[1];
                if (mode == 0)      { f0 = a0v + c0v;        f1 = a1v + c1v; }
                else if (mode == 1) { f0 = fabsf(a0v - c0v); f1 = fabsf(a1v - c1v); }
                else                { f0 = a0v * c0v;        f1 = a1v * c1v; }
            }
            unsigned short h0, l0, h1v, l1v;
            bf16split(f0, h0, l0);
            bf16split(f1, h1v, l1v);
            Ahi[pp * KB_STR + kk2] = packu(h0, h1v);
            Alo[pp * KB_STR + kk2] = packu(l0, l1v);
        }

        // stage W1 chunk hi/lo [n][k]
        #pragma unroll 4
        for (int idx = tid; idx < 96 * 32; idx += 256) {
            int n   = idx >> 5;
            int kk2 = idx & 31;
            const float* wp = W1 + (size_t)(D_Z + ch * 64 + kk2 * 2) * H1 + n;
            float w0 = wp[0], w1 = wp[H1];
            unsigned short h0, l0, h1v, l1v;
            bf16split(w0, h0, l0);
            bf16split(w1, h1v, l1v);
            Whi[n * KB_STR + kk2] = packu(h0, h1v);
            Wlo[n * KB_STR + kk2] = packu(l0, l1v);
        }
        __syncthreads();

        // 3 passes x 4 k16-steps
        #pragma unroll
        for (int pass = 0; pass < 3; pass++) {
            const uint32_t* Ab = (pass == 1) ? Alo : Ahi;
            const uint32_t* Bb = (pass == 2) ? Wlo : Whi;
            #pragma unroll
            for (int ks = 0; ks < 4; ks++) {
                int kw = ks * 8;
                uint32_t bfr[6][2];
                #pragma unroll
                for (int nt = 0; nt < 6; nt++) {
                    int n = ncol + nt * 8 + gid;
                    bfr[nt][0] = Bb[n * KB_STR + kw + tig];
                    bfr[nt][1] = Bb[n * KB_STR + kw + 4 + tig];
                }
                #pragma unroll
                for (int mt = 0; mt < 2; mt++) {
                    int r = mrow + mt * 16 + gid;
                    uint32_t a0 = Ab[(r)     * KB_STR + kw + tig];
                    uint32_t a1 = Ab[(r + 8) * KB_STR + kw + tig];
                    uint32_t a2 = Ab[(r)     * KB_STR + kw + 4 + tig];
                    uint32_t a3 = Ab[(r + 8) * KB_STR + kw + 4 + tig];
                    #pragma unroll
                    for (int nt = 0; nt < 6; nt++)
                        mma_bf16(c[mt][nt], a0, a1, a2, a3, bfr[nt][0], bfr[nt][1]);
                }
            }
        }
    }

    // epilogue: scatter accumulators to g_Cp
    #pragma unroll
    for (int mt = 0; mt < 2; mt++)
        #pragma unroll
        for (int rh = 0; rh < 2; rh++) {
            int row = mrow + mt * 16 + rh * 8 + gid;
            float* o = g_Cp + (size_t)(p0 + row) * H1;
            #pragma unroll
            for (int nt = 0; nt < 6; nt++) {
                int col = ncol + nt * 8 + tig * 2;
                *(float2*)(o + col) =
                    make_float2(c[mt][nt][rh * 2], c[mt][nt][rh * 2 + 1]);
            }
        }
}

// ---------------------------------------------------------------------------
// Kernel C (mma.sync bf16 hi/lo): out[b,p] = gelu(gelu(A+Cp)@W2+b2)@W3+b3
// (unchanged from round 9)
// ---------------------------------------------------------------------------
#define SA_STR 52
#define AHI_OFF 0
#define ALO_OFF 6656
#define BHI_OFF 13312
#define BLO_OFF 18304
#define AF_OFF  23296
#define B2_OFF  23392
#define W3_OFF  23488
#define PS_OFF  23584
#define KC_SMEM_BYTES ((23584 + 256) * 4)

__global__ void __launch_bounds__(256) kC(const float* __restrict__ W2,
                                          const float* __restrict__ b2,
                                          const float* __restrict__ W3,
                                          const float* __restrict__ b3,
                                          float* __restrict__ out) {
    extern __shared__ uint32_t smw[];
    uint32_t* Ahi = smw + AHI_OFF;
    uint32_t* Alo = smw + ALO_OFF;
    uint32_t* Bhi = smw + BHI_OFF;
    uint32_t* Blo = smw + BLO_OFF;
    float* Af  = (float*)(smw + AF_OFF);
    float* b2f = (float*)(smw + B2_OFF);
    float* W3f = (float*)(smw + W3_OFF);
    float* ps  = (float*)(smw + PS_OFF);

    int tid  = threadIdx.x;
    int wid  = tid >> 5;
    int lane = tid & 31;
    int gid  = lane >> 2;
    int tig  = lane & 3;
    int b    = blockIdx.y;
    int p0   = blockIdx.x * 128;

    if (tid < 96) {
        Af[tid]  = g_A[b * H1 + tid];
        b2f[tid] = b2[tid];
        W3f[tid] = W3[tid];
    }
    __syncthreads();

    for (int idx = tid; idx < 96 * 96; idx += 256) {
        int k = idx / 96, n = idx - k * 96;
        unsigned short h, l;
        bf16split(W2[idx], h, l);
        ((unsigned short*)Bhi)[n * (SA_STR * 2) + k] = h;
        ((unsigned short*)Blo)[n * (SA_STR * 2) + k] = l;
    }

    {
        int row = tid >> 1, half = tid & 1;
        const float4* cp4 = (const float4*)(g_Cp + (size_t)(p0 + row) * H1) + half * 12;
        uint32_t* ah = Ahi + row * SA_STR + half * 24;
        uint32_t* al = Alo + row * SA_STR + half * 24;
        #pragma unroll
        for (int q = 0; q < 12; q++) {
            float4 v = cp4[q];
            int k = half * 48 + q * 4;
            float g0 = gelu_exact(Af[k + 0] + v.x);
            float g1 = gelu_exact(Af[k + 1] + v.y);
            float g2 = gelu_exact(Af[k + 2] + v.z);
            float g3 = gelu_exact(Af[k + 3] + v.w);
            unsigned short h0, l0, h1v, l1v, h2, l2, h3, l3;
            bf16split(g0, h0, l0); bf16split(g1, h1v, l1v);
            bf16split(g2, h2, l2); bf16split(g3, h3, l3);
            ah[q * 2 + 0] = packu(h0, h1v);
            ah[q * 2 + 1] = packu(h2, h3);
            al[q * 2 + 0] = packu(l0, l1v);
            al[q * 2 + 1] = packu(l2, l3);
        }
    }
    __syncthreads();

    int mrow = (wid >> 1) * 32;
    int ncol = (wid & 1) * 48;

    float c[2][6][4];
    #pragma unroll
    for (int mt = 0; mt < 2; mt++)
        #pragma unroll
        for (int nt = 0; nt < 6; nt++)
            #pragma unroll
            for (int r = 0; r < 4; r++) c[mt][nt][r] = 0.f;

    #pragma unroll 1
    for (int pass = 0; pass < 3; pass++) {
        const uint32_t* Ab = (pass == 1) ? Alo : Ahi;
        const uint32_t* Bb = (pass == 2) ? Blo : Bhi;
        #pragma unroll
        for (int ks = 0; ks < 6; ks++) {
            int kw = ks * 8;
            uint32_t bfr[6][2];
            #pragma unroll
            for (int nt = 0; nt < 6; nt++) {
                int n = ncol + nt * 8 + gid;
                bfr[nt][0] = Bb[n * SA_STR + kw + tig];
                bfr[nt][1] = Bb[n * SA_STR + kw + 4 + tig];
            }
            #pragma unroll
            for (int mt = 0; mt < 2; mt++) {
                int r = mrow + mt * 16 + gid;
                uint32_t a0 = Ab[(r)     * SA_STR + kw + tig];
                uint32_t a1 = Ab[(r + 8) * SA_STR + kw + tig];
                uint32_t a2 = Ab[(r)     * SA_STR + kw + 4 + tig];
                uint32_t a3 = Ab[(r + 8) * SA_STR + kw + 4 + tig];
                #pragma unroll
                for (int nt = 0; nt < 6; nt++)
                    mma_bf16(c[mt][nt], a0, a1, a2, a3, bfr[nt][0], bfr[nt][1]);
            }
        }
    }

    #pragma unroll
    for (int mt = 0; mt < 2; mt++) {
        #pragma unroll
        for (int rh = 0; rh < 2; rh++) {
            float part = 0.f;
            #pragma unroll
            for (int nt = 0; nt < 6; nt++) {
                int col = ncol + nt * 8 + tig * 2;
                float v0 = c[mt][nt][rh * 2 + 0] + b2f[col];
                float v1 = c[mt][nt][rh * 2 + 1] + b2f[col + 1];
                part += gelu_exact(v0) * W3f[col];
                part += gelu_exact(v1) * W3f[col + 1];
            }
            part += __shfl_xor_sync(0xFFFFFFFF, part, 1);
            part += __shfl_xor_sync(0xFFFFFFFF, part, 2);
            if (tig == 0) {
                int row = mrow + mt * 16 + rh * 8 + gid;
                ps[(wid & 1) * 128 + row] = part;
            }
        }
    }
    __syncthreads();

    if (tid < 128) {
        float s = ps[tid] + ps[128 + tid] + b3[0];
        out[(size_t)b * PP + p0 + tid] = s;
    }
}

// ---------------------------------------------------------------------------
extern "C" void kernel_launch(void* const* d_in, const int* in_sizes, int n_in,
                              void* d_out, int out_size) {
    const float* g_q = (const float*)d_in[0];
    const float* Phi = (const float*)d_in[1];
    const void*  pin = (const void*)d_in[2];
    const float* rel = (const float*)d_in[3];
    const float* W1  = (const float*)d_in[4];
    const float* b1  = (const float*)d_in[5];
    const float* W2  = (const float*)d_in[6];
    const float* b2  = (const float*)d_in[7];
    const float* W3  = (const float*)d_in[8];
    const float* b3  = (const float*)d_in[9];
    float* out = (float*)d_out;

    cudaFuncSetAttribute(kB, cudaFuncAttributeMaxDynamicSharedMemorySize,
                         KB_SMEM_BYTES);
    cudaFuncSetAttribute(kC, cudaFuncAttributeMaxDynamicSharedMemorySize,
                         KC_SMEM_BYTES);

    kB<<<PP / 128, 256, KB_SMEM_BYTES>>>(Phi, pin, rel, W1);
    kA<<<BB, 768>>>(g_q, W1, b1);
    kC<<<dim3(PP / 128, BB), 256, KC_SMEM_BYTES>>>(W2, b2, W3, b3, out);
}

// round 11
// speedup vs baseline: 2.2672x; 1.3372x over previous
#include <cuda_runtime.h>
#include <cuda_bf16.h>
#include <math.h>
#include <stdint.h>

#define BB 16
#define PP 16384
#define MM 2048
#define D_Z 512
#define D_PHI 256
#define D_R 64
#define H1 96
#define H2 96

// scratch (no allocation allowed)
__device__ float g_A[BB * H1];
__device__ float g_Cp[PP * H1];
// precomputed bf16 hi/lo weights, [n][k2] layout (k2 = packed k-pair index)
__device__ uint32_t g_W1hi[96 * 416];
__device__ uint32_t g_W1lo[96 * 416];
__device__ uint32_t g_W2hi[96 * 48];
__device__ uint32_t g_W2lo[96 * 48];

__device__ __forceinline__ float gelu_exact(float x) {
    return 0.5f * x * (1.0f + erff(x * 0.70710678118654752440f));
}

// ---- bf16 split helpers ----
__device__ __forceinline__ void bf16split(float x, unsigned short& h, unsigned short& l) {
    __nv_bfloat16 bh = __float2bfloat16_rn(x);
    float fh = __bfloat162float(bh);
    __nv_bfloat16 bl = __float2bfloat16_rn(x - fh);
    h = __bfloat16_as_ushort(bh);
    l = __bfloat16_as_ushort(bl);
}
__device__ __forceinline__ uint32_t packu(unsigned short lo16, unsigned short hi16) {
    return (uint32_t)lo16 | ((uint32_t)hi16 << 16);
}

// bf16 mma.sync (sm_80+ baseline, legal on compute_100)
__device__ __forceinline__ void mma_bf16(float* c,
                                         uint32_t a0, uint32_t a1, uint32_t a2, uint32_t a3,
                                         uint32_t b0, uint32_t b1) {
    asm volatile(
        "mma.sync.aligned.m16n8k16.row.col.f32.bf16.bf16.f32 "
        "{%0,%1,%2,%3}, {%4,%5,%6,%7}, {%8,%9}, {%0,%1,%2,%3};"
        : "+f"(c[0]), "+f"(c[1]), "+f"(c[2]), "+f"(c[3])
        : "r"(a0), "r"(a1), "r"(a2), "r"(a3), "r"(b0), "r"(b1));
}

// ---------------------------------------------------------------------------
// Kernel P: precompute bf16 hi/lo splits of W1[512:,:] and W2, [n][k2] layout.
// ---------------------------------------------------------------------------
__global__ void kP(const float* __restrict__ W1, const float* __restrict__ W2) {
    int idx = blockIdx.x * blockDim.x + threadIdx.x;
    if (idx < 96 * 416) {
        int n = idx / 416, k2 = idx - n * 416;
        float w0 = W1[(size_t)(D_Z + 2 * k2) * H1 + n];
        float w1 = W1[(size_t)(D_Z + 2 * k2 + 1) * H1 + n];
        unsigned short h0, l0, h1v, l1v;
        bf16split(w0, h0, l0);
        bf16split(w1, h1v, l1v);
        g_W1hi[idx] = packu(h0, h1v);
        g_W1lo[idx] = packu(l0, l1v);
    } else if (idx < 96 * 416 + 96 * 48) {
        int t = idx - 96 * 416;
        int n = t / 48, k2 = t - n * 48;
        float w0 = W2[(size_t)(2 * k2) * H2 + n];
        float w1 = W2[(size_t)(2 * k2 + 1) * H2 + n];
        unsigned short h0, l0, h1v, l1v;
        bf16split(w0, h0, l0);
        bf16split(w1, h1v, l1v);
        g_W2hi[t] = packu(h0, h1v);
        g_W2lo[t] = packu(l0, l1v);
    }
}

// ---------------------------------------------------------------------------
// Kernel A: A[b,j] = b1[j] + sum_k g_q[b,k] * W1[k,j]
// ---------------------------------------------------------------------------
__global__ void __launch_bounds__(768) kA(const float* __restrict__ g_q,
                                          const float* __restrict__ W1,
                                          const float* __restrict__ b1) {
    __shared__ float gq_sh[D_Z];
    __shared__ float psum[7 * 96];
    int b = blockIdx.x;
    int tid = threadIdx.x;
    for (int t = tid; t < D_Z; t += 768) gq_sh[t] = g_q[b * D_Z + t];
    __syncthreads();
    int ks = tid / 96, j = tid % 96;
    float s = 0.f;
    const float* w = W1 + (size_t)(ks * 64) * H1 + j;
    #pragma unroll 8
    for (int k = 0; k < 64; k++)
        s += gq_sh[ks * 64 + k] * w[(size_t)k * H1];
    if (ks > 0) psum[(ks - 1) * 96 + j] = s;
    __syncthreads();
    if (ks == 0) {
        #pragma unroll
        for (int i = 0; i < 7; i++) s += psum[i * 96 + j];
        g_A[b * H1 + j] = s + b1[j];
    }
}

// ---------------------------------------------------------------------------
// Kernel B (mma.sync bf16 hi/lo): Cp[p,:] = feat(p,:) @ W1[512:,:]
// Block = 64 pairs, 256 threads (8 warps), grid = 256 (>=2 blocks/SM).
// Warp tile 16 rows x 48 cols (24 fp32 acc). K = 832 in 13 chunks of 64.
// Per chunk: build features fp32 -> split hi/lo into smem [row][k];
// copy precomputed W1 hi/lo chunk from global; 3 passes x 4 k16-steps.
// Static smem 46.6 KB; __launch_bounds__(256,2) keeps regs <= 128.
// ---------------------------------------------------------------------------
#define KB_STR 36
#define KB_ROWS 64

__global__ void __launch_bounds__(256, 2) kB(const float* __restrict__ Phi,
                                             const void* __restrict__ pair_index,
                                             const float* __restrict__ rel) {
    __shared__ uint32_t Ahi[KB_ROWS * KB_STR];   // 2304
    __shared__ uint32_t Alo[KB_ROWS * KB_STR];   // 2304
    __shared__ uint32_t Whi[96 * KB_STR];        // 3456
    __shared__ uint32_t Wlo[96 * KB_STR];        // 3456
    __shared__ int pi_sh[KB_ROWS * 2];

    int tid  = threadIdx.x;
    int wid  = tid >> 5;
    int lane = tid & 31;
    int gid  = lane >> 2;
    int tig  = lane & 3;
    int p0   = blockIdx.x * KB_ROWS;

    // ---- pair_index dtype detection + load (128 values) ----
    {
        const int* p32 = (const int*)pair_index;
        int w = 0;
        if (tid < KB_ROWS * 2) w = p32[(size_t)p0 * 2 + tid];
        int any_odd = __syncthreads_or((tid & 1) ? w : 0);
        if (tid < KB_ROWS * 2) {
            int v;
            if (any_odd != 0) v = w;
            else {
                const long long* p64 = (const long long*)pair_index;
                v = (int)p64[(size_t)p0 * 2 + tid];
            }
            v = v < 0 ? 0 : (v >= MM ? MM - 1 : v);
            pi_sh[tid] = v;
        }
    }

    int mrow = (wid >> 1) * 16;        // 4 row groups x 16
    int ncol = (wid & 1) * 48;         // 2 col halves x 48

    float c[6][4];
    #pragma unroll
    for (int nt = 0; nt < 6; nt++)
        #pragma unroll
        for (int r = 0; r < 4; r++) c[nt][r] = 0.f;

    for (int ch = 0; ch < 13; ch++) {
        int mode  = ch >> 2;           // 0 sum, 1 absdiff, 2 prod, 3 relation
        int cbase = (ch & 3) * 64;
        __syncthreads();

        // build feature chunk (split bf16 hi/lo), 2 k per thread-step
        #pragma unroll 2
        for (int idx = tid; idx < KB_ROWS * 32; idx += 256) {
            int pp  = idx >> 5;
            int kk2 = idx & 31;
            float f0, f1;
            if (mode == 3) {
                const float* rp = rel + (size_t)(p0 + pp) * D_R + kk2 * 2;
                f0 = rp[0]; f1 = rp[1];
            } else {
                int i0 = pi_sh[pp * 2];
                int j0 = pi_sh[pp * 2 + 1];
                const float* pi_ = Phi + (size_t)i0 * D_PHI + cbase + kk2 * 2;
                const float* pj_ = Phi + (size_t)j0 * D_PHI + cbase + kk2 * 2;
                float a0v = pi_[0], a1v = pi_[1];
                float c0v = pj_[0], c1v = pj_[1];
                if (mode == 0)      { f0 = a0v + c0v;        f1 = a1v + c1v; }
                else if (mode == 1) { f0 = fabsf(a0v - c0v); f1 = fabsf(a1v - c1v); }
                else                { f0 = a0v * c0v;        f1 = a1v * c1v; }
            }
            unsigned short h0, l0, h1v, l1v;
            bf16split(f0, h0, l0);
            bf16split(f1, h1v, l1v);
            Ahi[pp * KB_STR + kk2] = packu(h0, h1v);
            Alo[pp * KB_STR + kk2] = packu(l0, l1v);
        }

        // copy precomputed W1 chunk hi/lo (coalesced u32)
        #pragma unroll 4
        for (int idx = tid; idx < 96 * 32; idx += 256) {
            int n   = idx >> 5;
            int kk2 = idx & 31;
            Whi[n * KB_STR + kk2] = g_W1hi[n * 416 + ch * 32 + kk2];
            Wlo[n * KB_STR + kk2] = g_W1lo[n * 416 + ch * 32 + kk2];
        }
        __syncthreads();

        // 3 passes x 4 k16-steps
        #pragma unroll
        for (int pass = 0; pass < 3; pass++) {
            const uint32_t* Ab = (pass == 1) ? Alo : Ahi;
            const uint32_t* Bb = (pass == 2) ? Wlo : Whi;
            #pragma unroll
            for (int ks = 0; ks < 4; ks++) {
                int kw = ks * 8;
                int r = mrow + gid;
                uint32_t a0 = Ab[(r)     * KB_STR + kw + tig];
                uint32_t a1 = Ab[(r + 8) * KB_STR + kw + tig];
                uint32_t a2 = Ab[(r)     * KB_STR + kw + 4 + tig];
                uint32_t a3 = Ab[(r + 8) * KB_STR + kw + 4 + tig];
                #pragma unroll
                for (int nt = 0; nt < 6; nt++) {
                    int n = ncol + nt * 8 + gid;
                    uint32_t b0 = Bb[n * KB_STR + kw + tig];
                    uint32_t b1v = Bb[n * KB_STR + kw + 4 + tig];
                    mma_bf16(c[nt], a0, a1, a2, a3, b0, b1v);
                }
            }
        }
    }

    // epilogue: scatter accumulators to g_Cp
    #pragma unroll
    for (int rh = 0; rh < 2; rh++) {
        int row = mrow + rh * 8 + gid;
        float* o = g_Cp + (size_t)(p0 + row) * H1;
        #pragma unroll
        for (int nt = 0; nt < 6; nt++) {
            int col = ncol + nt * 8 + tig * 2;
            *(float2*)(o + col) = make_float2(c[nt][rh * 2], c[nt][rh * 2 + 1]);
        }
    }
}

// ---------------------------------------------------------------------------
// Kernel C (mma.sync bf16 hi/lo): out[b,p] = gelu(gelu(A+Cp)@W2+b2)@W3+b3
// W2 hi/lo now copied from precomputed globals (coalesced u32).
// ---------------------------------------------------------------------------
#define SA_STR 52
#define AHI_OFF 0
#define ALO_OFF 6656
#define BHI_OFF 13312
#define BLO_OFF 18304
#define AF_OFF  23296
#define B2_OFF  23392
#define W3_OFF  23488
#define PS_OFF  23584
#define KC_SMEM_BYTES ((23584 + 256) * 4)

__global__ void __launch_bounds__(256) kC(const float* __restrict__ b2,
                                          const float* __restrict__ W3,
                                          const float* __restrict__ b3,
                                          float* __restrict__ out) {
    extern __shared__ uint32_t smw[];
    uint32_t* Ahi = smw + AHI_OFF;
    uint32_t* Alo = smw + ALO_OFF;
    uint32_t* Bhi = smw + BHI_OFF;
    uint32_t* Blo = smw + BLO_OFF;
    float* Af  = (float*)(smw + AF_OFF);
    float* b2f = (float*)(smw + B2_OFF);
    float* W3f = (float*)(smw + W3_OFF);
    float* ps  = (float*)(smw + PS_OFF);

    int tid  = threadIdx.x;
    int wid  = tid >> 5;
    int lane = tid & 31;
    int gid  = lane >> 2;
    int tig  = lane & 3;
    int b    = blockIdx.y;
    int p0   = blockIdx.x * 128;

    if (tid < 96) {
        Af[tid]  = g_A[b * H1 + tid];
        b2f[tid] = b2[tid];
        W3f[tid] = W3[tid];
    }
    // copy precomputed W2 hi/lo (coalesced u32)
    for (int idx = tid; idx < 96 * 48; idx += 256) {
        int n = idx / 48, k2 = idx - n * 48;
        Bhi[n * SA_STR + k2] = g_W2hi[idx];
        Blo[n * SA_STR + k2] = g_W2lo[idx];
    }
    __syncthreads();

    // h1 = gelu(Af + Cp), split, store [row][k] (thread = row x k-half)
    {
        int row = tid >> 1, half = tid & 1;
        const float4* cp4 = (const float4*)(g_Cp + (size_t)(p0 + row) * H1) + half * 12;
        uint32_t* ah = Ahi + row * SA_STR + half * 24;
        uint32_t* al = Alo + row * SA_STR + half * 24;
        #pragma unroll
        for (int q = 0; q < 12; q++) {
            float4 v = cp4[q];
            int k = half * 48 + q * 4;
            float g0 = gelu_exact(Af[k + 0] + v.x);
            float g1 = gelu_exact(Af[k + 1] + v.y);
            float g2 = gelu_exact(Af[k + 2] + v.z);
            float g3 = gelu_exact(Af[k + 3] + v.w);
            unsigned short h0, l0, h1v, l1v, h2, l2, h3, l3;
            bf16split(g0, h0, l0); bf16split(g1, h1v, l1v);
            bf16split(g2, h2, l2); bf16split(g3, h3, l3);
            ah[q * 2 + 0] = packu(h0, h1v);
            ah[q * 2 + 1] = packu(h2, h3);
            al[q * 2 + 0] = packu(l0, l1v);
            al[q * 2 + 1] = packu(l2, l3);
        }
    }
    __syncthreads();

    int mrow = (wid >> 1) * 32;
    int ncol = (wid & 1) * 48;

    float c[2][6][4];
    #pragma unroll
    for (int mt = 0; mt < 2; mt++)
        #pragma unroll
        for (int nt = 0; nt < 6; nt++)
            #pragma unroll
            for (int r = 0; r < 4; r++) c[mt][nt][r] = 0.f;

    #pragma unroll 1
    for (int pass = 0; pass < 3; pass++) {
        const uint32_t* Ab = (pass == 1) ? Alo : Ahi;
        const uint32_t* Bb = (pass == 2) ? Blo : Bhi;
        #pragma unroll
        for (int ks = 0; ks < 6; ks++) {
            int kw = ks * 8;
            uint32_t bfr[6][2];
            #pragma unroll
            for (int nt = 0; nt < 6; nt++) {
                int n = ncol + nt * 8 + gid;
                bfr[nt][0] = Bb[n * SA_STR + kw + tig];
                bfr[nt][1] = Bb[n * SA_STR + kw + 4 + tig];
            }
            #pragma unroll
            for (int mt = 0; mt < 2; mt++) {
                int r = mrow + mt * 16 + gid;
                uint32_t a0 = Ab[(r)     * SA_STR + kw + tig];
                uint32_t a1 = Ab[(r + 8) * SA_STR + kw + tig];
                uint32_t a2 = Ab[(r)     * SA_STR + kw + 4 + tig];
                uint32_t a3 = Ab[(r + 8) * SA_STR + kw + 4 + tig];
                #pragma unroll
                for (int nt = 0; nt < 6; nt++)
                    mma_bf16(c[mt][nt], a0, a1, a2, a3, bfr[nt][0], bfr[nt][1]);
            }
        }
    }

    #pragma unroll
    for (int mt = 0; mt < 2; mt++) {
        #pragma unroll
        for (int rh = 0; rh < 2; rh++) {
            float part = 0.f;
            #pragma unroll
            for (int nt = 0; nt < 6; nt++) {
                int col = ncol + nt * 8 + tig * 2;
                float v0 = c[mt][nt][rh * 2 + 0] + b2f[col];
                float v1 = c[mt][nt][rh * 2 + 1] + b2f[col + 1];
                part += gelu_exact(v0) * W3f[col];
                part += gelu_exact(v1) * W3f[col + 1];
            }
            part += __shfl_xor_sync(0xFFFFFFFF, part, 1);
            part += __shfl_xor_sync(0xFFFFFFFF, part, 2);
            if (tig == 0) {
                int row = mrow + mt * 16 + rh * 8 + gid;
                ps[(wid & 1) * 128 + row] = part;
            }
        }
    }
    __syncthreads();

    if (tid < 128) {
        float s = ps[tid] + ps[128 + tid] + b3[0];
        out[(size_t)b * PP + p0 + tid] = s;
    }
}

// ---------------------------------------------------------------------------
extern "C" void kernel_launch(void* const* d_in, const int* in_sizes, int n_in,
                              void* d_out, int out_size) {
    const float* g_q = (const float*)d_in[0];
    const float* Phi = (const float*)d_in[1];
    const void*  pin = (const void*)d_in[2];
    const float* rel = (const float*)d_in[3];
    const float* W1  = (const float*)d_in[4];
    const float* b1  = (const float*)d_in[5];
    const float* W2  = (const float*)d_in[6];
    const float* b2  = (const float*)d_in[7];
    const float* W3  = (const float*)d_in[8];
    const float* b3  = (const float*)d_in[9];
    float* out = (float*)d_out;

    cudaFuncSetAttribute(kC, cudaFuncAttributeMaxDynamicSharedMemorySize,
                         KC_SMEM_BYTES);

    kP<<<(96 * 416 + 96 * 48 + 255) / 256, 256>>>(W1, W2);
    kB<<<PP / KB_ROWS, 256>>>(Phi, pin, rel);
    kA<<<BB, 768>>>(g_q, W1, b1);
    kC<<<dim3(PP / 128, BB), 256, KC_SMEM_BYTES>>>(b2, W3, b3, out);
}